// round 11
// baseline (speedup 1.0000x reference)
#include <cuda_runtime.h>

// Problem constants (fixed by the reference)
#define BB 8
#define NT 256
#define WHD 21
#define PP 441          // WHD*WHD
#define PAD 23          // zero-padded patch dim
#define IMW 1024
#define ITERS 20
#define NTHREADS 64     // 2 warps per track
#define PTS 7           // points per thread: 64*7 = 448 >= 441

__global__ __launch_bounds__(NTHREADS)
void mt_kernel(const float* __restrict__ track,
               const float* __restrict__ imgs,
               float* __restrict__ out)
{
    const int id = blockIdx.x;           // 0 .. B*NT-1, one CTA (2 warps) per track
    const int b = id >> 8;               // id / NT (NT = 256)
    const int t = id & 255;

    const float* f0 = imgs + (size_t)b * 2 * IMW * IMW;   // frame 0 (H==W==1024)
    const float* f1 = f0 + (size_t)(IMW * IMW);           // frame 1

    __shared__ float sP[PAD * PAD];      // zero-padded sampled patch
    __shared__ float sRed[2][5];         // per-warp partial sums

    const int tid  = threadIdx.x;
    const int lane = tid & 31;
    const int wid  = tid >> 5;

    // per-thread shift state (uniform across the CTA)
    float sx, sy;
    {
        const float SCALE = 21.0f / 1024.0f;   // exact in fp32
        sx = track[b * (NT * 2) + t * 2 + 0] / SCALE;
        sy = track[b * (NT * 2) + t * 2 + 1] / SCALE;
    }

    // zero the padded patch once; border stays zero forever
    #pragma unroll
    for (int k = tid; k < PAD * PAD; k += NTHREADS) sP[k] = 0.0f;

    // exact replication of the reference bilinear (clip indices, then weights)
    auto bilinear = [&](const float* __restrict__ f, float gx, float gy,
                        float ssx, float ssy) -> float {
        float x = (gx + ssx) * 10.5f;    // WH*0.5
        float y = (gy + ssy) * 10.5f;
        float fx = floorf(x);
        float fy = floorf(y);
        float x0 = fminf(fmaxf(fx,        0.0f), 1023.0f);
        float x1 = fminf(fmaxf(fx + 1.0f, 0.0f), 1023.0f);
        float y0 = fminf(fmaxf(fy,        0.0f), 1023.0f);
        float y1 = fminf(fmaxf(fy + 1.0f, 0.0f), 1023.0f);
        float wa = (y1 - y) * (x1 - x);
        float wb = (y1 - y) * (x  - x0);
        float wc = (y  - y0) * (x1 - x);
        float wd = (y  - y0) * (x  - x0);
        int xi0 = (int)x0, xi1 = (int)x1;
        int yi0 = (int)y0, yi1 = (int)y1;
        const float* r0 = f + yi0 * IMW;
        const float* r1 = f + yi1 * IMW;
        return wa * __ldg(r0 + xi0) + wb * __ldg(r0 + xi1)
             + wc * __ldg(r1 + xi0) + wd * __ldg(r1 + xi1);
    };

    // 'second' (frame 1 at initial positions) — fixed for all iterations
    float second[PTS];
    #pragma unroll
    for (int k = 0; k < PTS; ++k) {
        const int p = tid + k * NTHREADS;
        second[k] = 0.0f;
        if (p < PP) {
            const int i = p / WHD;
            const int j = p - i * WHD;
            const float gx = -1.0f + 0.1f * (float)j;
            const float gy = -1.0f + 0.1f * (float)i;
            second[k] = bilinear(f1, gx, gy, sx, sy);
            out[((((size_t)b * 2) + 1) * NT + t) * PP + p] = second[k];
        }
    }

    __syncthreads();   // padded border zeros visible

    for (int it = 0; it < ITERS; ++it) {
        // ---- sample f0 (tid-consecutive points -> coalesced L1 gathers) ----
        float o0[PTS];
        #pragma unroll
        for (int k = 0; k < PTS; ++k) {
            const int p = tid + k * NTHREADS;
            if (p < PP) {
                const int i = p / WHD;
                const int j = p - i * WHD;
                const float gx = -1.0f + 0.1f * (float)j;
                const float gy = -1.0f + 0.1f * (float)i;
                o0[k] = bilinear(f0, gx, gy, sx, sy);
                sP[(i + 1) * PAD + (j + 1)] = o0[k];
            }
        }
        __syncthreads();                       // sync A: patch visible

        // ---- per-point zero-padded Sobel stencil + local accumulation ----
        float v0 = 0.f, v1 = 0.f, v2 = 0.f, v3 = 0.f, v4 = 0.f;
        #pragma unroll
        for (int k = 0; k < PTS; ++k) {
            const int p = tid + k * NTHREADS;
            if (p < PP) {
                const int i = p / WHD;
                const int j = p - i * WHD;
                const int pb = (i + 1) * PAD + (j + 1);
                float a00 = sP[pb - PAD - 1], a01 = sP[pb - PAD], a02 = sP[pb - PAD + 1];
                float a10 = sP[pb - 1],                            a12 = sP[pb + 1];
                float a20 = sP[pb + PAD - 1], a21 = sP[pb + PAD], a22 = sP[pb + PAD + 1];
                float Ix = (a02 - a00) + 2.0f * (a12 - a10) + (a22 - a20);
                float Iy = (a20 - a00) + 2.0f * (a21 - a01) + (a22 - a02);
                float It = second[k] - o0[k];
                v0 = fmaf(Ix, Ix, v0);
                v1 = fmaf(Iy, Iy, v1);
                v2 = fmaf(Ix, Iy, v2);
                v3 = fmaf(Ix, It, v3);
                v4 = fmaf(Iy, It, v4);
            }
        }

        // ---- butterfly reduction within each warp ----
        #pragma unroll
        for (int off = 16; off; off >>= 1) {
            v0 += __shfl_xor_sync(0xffffffffu, v0, off);
            v1 += __shfl_xor_sync(0xffffffffu, v1, off);
            v2 += __shfl_xor_sync(0xffffffffu, v2, off);
            v3 += __shfl_xor_sync(0xffffffffu, v3, off);
            v4 += __shfl_xor_sync(0xffffffffu, v4, off);
        }
        if (lane == 0) {
            sRed[wid][0] = v0;
            sRed[wid][1] = v1;
            sRed[wid][2] = v2;
            sRed[wid][3] = v3;
            sRed[wid][4] = v4;
        }
        __syncthreads();                       // sync B: partials visible

        // ---- combine the two warps' partials; every thread solves locally ----
        float Ix2  = sRed[0][0] + sRed[1][0];
        float Iy2  = sRed[0][1] + sRed[1][1];
        float IxIy = sRed[0][2] + sRed[1][2];
        float IxIt = sRed[0][3] + sRed[1][3];
        float IyIt = sRed[0][4] + sRed[1][4];

        float det_inv = 1.0f / (Ix2 * Iy2 - IxIy * IxIy);
        float Vx = det_inv * (Iy2    * (-IxIt) + (-IxIy) * (-IyIt));
        float Vy = det_inv * ((-IxIy) * (-IxIt) + Ix2    * (-IyIt));
        sx = sx - Vx;
        sy = sy - Vy;
    }

    // final sample of frame 0 at converged positions
    #pragma unroll
    for (int k = 0; k < PTS; ++k) {
        const int p = tid + k * NTHREADS;
        if (p < PP) {
            const int i = p / WHD;
            const int j = p - i * WHD;
            const float gx = -1.0f + 0.1f * (float)j;
            const float gy = -1.0f + 0.1f * (float)i;
            float o0 = bilinear(f0, gx, gy, sx, sy);
            out[((((size_t)b * 2) + 0) * NT + t) * PP + p] = o0;
        }
    }
}

extern "C" void kernel_launch(void* const* d_in, const int* in_sizes, int n_in,
                              void* d_out, int out_size)
{
    // track_locs: 8*512 = 4096 floats; imgs: 8*2*1024*1024 floats.
    const float* track;
    const float* imgs;
    if (in_sizes[0] < in_sizes[1]) {
        track = (const float*)d_in[0];
        imgs  = (const float*)d_in[1];
    } else {
        track = (const float*)d_in[1];
        imgs  = (const float*)d_in[0];
    }
    float* out = (float*)d_out;
    mt_kernel<<<BB * NT, NTHREADS>>>(track, imgs, out);
}